// round 17
// baseline (speedup 1.0000x reference)
#include <cuda_runtime.h>
#include <cuda_fp16.h>
#include <math.h>
#include <stddef.h>
#include <stdint.h>

// B=256, T=512, V=64(65 rows), E=128, H=256, 3H=768, D=2

// ---------------- PTX helpers (baseline ISA only: sm_80-era, safe on sm_103) ----------------
__device__ __forceinline__ uint32_t smem_to_u32(const void* p) {
    uint32_t a;
    asm("{ .reg .u64 t; cvta.to.shared.u64 t, %1; cvt.u32.u64 %0, t; }" : "=r"(a) : "l"(p));
    return a;
}
__device__ __forceinline__ void cp16(uint32_t s, const void* g) {
    asm volatile("cp.async.cg.shared.global [%0], [%1], 16;" :: "r"(s), "l"(g) : "memory");
}
#define CP_COMMIT() asm volatile("cp.async.commit_group;" ::: "memory")
#define CP_WAIT(n)  asm volatile("cp.async.wait_group %0;" :: "n"(n) : "memory")
#define LDSM_X4(r0, r1, r2, r3, addr) \
    asm volatile("ldmatrix.sync.aligned.m8n8.x4.shared.b16 {%0,%1,%2,%3}, [%4];" \
        : "=r"(r0), "=r"(r1), "=r"(r2), "=r"(r3) : "r"(addr))
#define LDSM_X2(r0, r1, addr) \
    asm volatile("ldmatrix.sync.aligned.m8n8.x2.shared.b16 {%0,%1}, [%2];" \
        : "=r"(r0), "=r"(r1) : "r"(addr))

// fp16 MMA, fp32 accumulate
__device__ __forceinline__ void mma16816h(float* c, const uint32_t* a, const uint32_t* b) {
    asm volatile(
        "mma.sync.aligned.m16n8k16.row.col.f32.f16.f16.f32 "
        "{%0,%1,%2,%3}, {%4,%5,%6,%7}, {%8,%9}, {%0,%1,%2,%3};"
        : "+f"(c[0]), "+f"(c[1]), "+f"(c[2]), "+f"(c[3])
        : "r"(a[0]), "r"(a[1]), "r"(a[2]), "r"(a[3]), "r"(b[0]), "r"(b[1]));
}

#define SWZ128(b) ((b) ^ (((b) >> 3) & 0x70))

__device__ __forceinline__ float tanh_ap(float x) {
    float y;
    asm("tanh.approx.f32 %0, %1;" : "=f"(y) : "f"(x));
    return y;
}
__device__ __forceinline__ float fsig(float x) {
    return fmaf(tanh_ap(0.5f*x), 0.5f, 0.5f);
}
__device__ __forceinline__ float ftanh(float x) {
    return __fdividef(2.f, 1.f + __expf(-2.f*x)) - 1.f;
}

// ---------------- static scratch ----------------
__device__ float d_ptab [2*65*768];
__device__ float d_xp1  [2*512*256*768];
__device__ float d_fc1p [512*256*128];
__device__ __half d_h1f[67108864];     // layer-0 output, fp16 [t][b][2H]
__device__ __half d_h2f[67108864];     // layer-1 output, fp16
__device__ __half d_wihf[786432];
__device__ __half d_W1f[33554432];
__device__ unsigned d_flags[4096];     // [16 groups][8 slots][32 pad]

__global__ void reset_bar_kernel() {
    d_flags[blockIdx.x*256 + threadIdx.x] = 0u;
}

// consumer-side poll: 8 lanes poll the 8 peer flags of the group
__device__ __forceinline__ void poll_group(int gid, unsigned target, int lane) {
    if (lane < 8) {
        const unsigned* f = d_flags + (gid*8 + lane)*32;
        unsigned v;
        while (true) {
            asm volatile("ld.global.acquire.gpu.u32 %0, [%1];" : "=r"(v) : "l"(f));
            if (v >= target) break;
            __nanosleep(20);
        }
    }
    __syncwarp();
}

// ---------------- L0 proj table ----------------
__global__ void __launch_bounds__(256) proj0_kernel(const float* __restrict__ emb,
                                                    const float* __restrict__ wih,
                                                    const float* __restrict__ bih) {
    const int d = blockIdx.x / 65;
    const int v = blockIdx.x % 65;
    __shared__ float es[128];
    if (threadIdx.x < 128) es[threadIdx.x] = emb[v*128 + threadIdx.x];
    __syncthreads();
    for (int g = threadIdx.x; g < 768; g += 256) {
        const float* w = wih + ((size_t)d*768 + g)*128;
        float s = bih[d*768 + g];
        #pragma unroll 4
        for (int e = 0; e < 128; e++) s += es[e]*__ldg(w + e);
        d_ptab[((size_t)d*65 + v)*768 + g] = s;
    }
}

// ---------------- fp32 -> fp16 convert (weights) ----------------
__global__ void __launch_bounds__(256) cvt_kernel(const float* __restrict__ x,
        __half* __restrict__ o, size_t n4) {
    size_t i = (size_t)blockIdx.x*256 + threadIdx.x;
    size_t stride = (size_t)gridDim.x*256;
    for (; i < n4; i += stride) {
        float4 v = __ldg((const float4*)x + i);
        __half2 h01 = __floats2half2_rn(v.x, v.y);
        __half2 h23 = __floats2half2_rn(v.z, v.w);
        uint2 w;
        w.x = *(uint32_t*)&h01; w.y = *(uint32_t*)&h23;
        ((uint2*)o)[i] = w;
    }
}

// ---------------- MMA recurrence (both layers) ----------------
// 128 CTAs = dir(2) x batch-slice(8 x 32 rows) x unit-slice(8 x 32 units)
// Per step: G[32 x 96] = h[32 x 256] @ W[96 x 256]^T, single-pass fp16 mma.
// W fragments hoisted to registers (loaded once from smem preload region).
// SMEM (1024-aligned base):
//   WF  @ 0     : 49152 (init preload only; dead after hoist)
//   HF  @ 49152 : 16384 (fp16 h tile, 4 chunks x 32rows x 128B)
//   G   @ 65536 : 32 x 100 floats = 12800
//   HPREV@78336 : 32 x 36 floats  = 4608
#define RECM_SMEM (82944 + 1024)

template<int LAYER>
__global__ void __launch_bounds__(256, 1) rec_mma_kernel(
    const int* __restrict__ inputs,
    const float* __restrict__ w_hh,
    const float* __restrict__ b_hh) {
    extern __shared__ char sm_raw[];
    __shared__ float bhh_s[96];
    const uint32_t raw  = smem_to_u32(sm_raw);
    const uint32_t base = (raw + 1023u) & ~1023u;
    char* sb = sm_raw + (base - raw);
    float* Gs    = (float*)(sb + 65536);
    float* Hprev = (float*)(sb + 78336);

    const int bid = blockIdx.x;
    const int dir = bid >> 6;
    const int rem = bid & 63;
    const int bs  = rem >> 3;
    const int us  = rem & 7;
    const int b0  = bs * 32;
    const int j0  = us * 32;
    const int gid = dir*8 + bs;
    const int tid = threadIdx.x;
    const int lane = tid & 31;
    const int wid  = tid >> 5;

    // ---- one-time: W_hh slice -> fp16 swizzled smem (gate-major rows) ----
    {
        const int k0 = (tid & 7) * 32;
        #pragma unroll
        for (int rr = 0; rr < 3; rr++) {
            const int lr = rr*32 + (tid >> 3);
            const int g  = lr >> 5;
            const float* src = w_hh + ((size_t)dir*768 + g*256 + j0 + (lr & 31))*256 + k0;
            const uint32_t cb = (uint32_t)(k0 >> 6)*12288u + (uint32_t)lr*128u + (uint32_t)(k0 & 63)*2u;
            #pragma unroll
            for (int q = 0; q < 8; q++) {
                float4 v = __ldg((const float4*)src + q);
                __half2 h01 = __floats2half2_rn(v.x, v.y);
                __half2 h23 = __floats2half2_rn(v.z, v.w);
                uint2 hh;
                hh.x = *(uint32_t*)&h01; hh.y = *(uint32_t*)&h23;
                *(uint2*)(sb + SWZ128(cb + q*8)) = hh;
            }
        }
    }
    if (tid < 96) bhh_s[tid] = b_hh[dir*768 + (tid>>5)*256 + j0 + (tid & 31)];
    // zero h tile + hprev
    for (int i = tid; i < 1024; i += 256)
        ((uint4*)(sb + 49152))[i] = make_uint4(0,0,0,0);
    for (int i = tid; i < 1152; i += 256)
        Hprev[i] = 0.f;
    __syncthreads();

    // per-thread nonlinearity mapping
    const int bb = tid >> 3;
    const int ju = (tid & 7) * 4;
    const int bg = b0 + bb;

    // MMA lane mappings
    const int wm = wid >> 2, wn = wid & 3;
    const int lrow = lane & 15, kseg = lane >> 4;
    const int g8 = lane >> 3, lr8 = lane & 7;
    const int nrx4 = ((g8 >> 1) & 1)*8 + lr8;
    const int ksx4 = g8 & 1;
    const int lx = lane & 15;
    const int rowb2 = lx & 7, kh2 = (lx >> 3) & 1;

    // ---- hoist W B-fragments into registers (step-invariant, 96 regs) ----
    uint32_t Bh4[16][4], Bh2[16][2];
    #pragma unroll
    for (int ks = 0; ks < 16; ks++) {
        const int ck = ks >> 2, ki = ks & 3;
        const uint32_t bcb = base + (uint32_t)ck*12288u;
        const uint32_t b4 = bcb +
            SWZ128((uint32_t)((wn*24 + nrx4)*128 + ki*32 + ksx4*16));
        const uint32_t b2 = bcb +
            SWZ128((uint32_t)((wn*24 + 16 + rowb2)*128 + ki*32 + kh2*16));
        LDSM_X4(Bh4[ks][0], Bh4[ks][1], Bh4[ks][2], Bh4[ks][3], b4);
        LDSM_X2(Bh2[ks][0], Bh2[ks][1], b2);
    }

    __half* obf = (LAYER == 0) ? d_h1f : d_h2f;
    const unsigned LB = (unsigned)(LAYER * 512);

    for (int s_ = 0; s_ < 512; s_++) {
        // prefetch x-projections (independent of peers -> issue before poll)
        const int t_in = (dir == 0) ? s_ : (511 - s_);
        float4 xr4, xz4, xn4;
        if (LAYER == 0) {
            const int tok = __ldg(inputs + bg*512 + t_in);
            const float* pt = d_ptab + ((size_t)dir*65 + tok)*768 + j0 + ju;
            xr4 = __ldg((const float4*)(pt));
            xz4 = __ldg((const float4*)(pt + 256));
            xn4 = __ldg((const float4*)(pt + 512));
        } else {
            const float* xp = d_xp1 + ((size_t)dir*131072 + (size_t)t_in*256 + bg)*768 + j0 + ju;
            xr4 = __ldg((const float4*)(xp));
            xz4 = __ldg((const float4*)(xp + 256));
            xn4 = __ldg((const float4*)(xp + 512));
        }

        if (s_ > 0) {
            poll_group(gid, LB + (unsigned)s_, lane);
            // read peers' h (fp16) from output buffer at t_prev (row stride 512)
            const int t_prev = (dir == 0) ? (s_ - 1) : (512 - s_);
            const __half* ghf = obf + ((size_t)t_prev*256 + b0)*512 + (size_t)dir*256;
            const int r  = tid >> 3;            // 0..31 (batch row)
            const int sg = tid & 7;             // 16B segment within 64-col chunk
            #pragma unroll
            for (int ck = 0; ck < 4; ck++) {
                uint32_t dst = SWZ128((uint32_t)(ck*4096 + r*128 + sg*16));
                size_t gofs = (size_t)r*512 + (size_t)ck*64 + (size_t)sg*8;
                cp16(base + 49152u + dst, ghf + gofs);
                if (ck == 1) CP_COMMIT();
            }
            CP_COMMIT();
        }

        // ---- MMA: G = h @ W^T, single-pass fp16 (W from registers) ----
        float c[3][4];
        #pragma unroll
        for (int fn = 0; fn < 3; fn++)
            #pragma unroll
            for (int q = 0; q < 4; q++) c[fn][q] = 0.f;

        #pragma unroll
        for (int half = 0; half < 2; half++) {
            if (s_ > 0) { if (half == 0) { CP_WAIT(1); } else { CP_WAIT(0); } }
            __syncthreads();
            #pragma unroll
            for (int ks8 = 0; ks8 < 8; ks8++) {
                const int ks = half*8 + ks8;
                const int ck = ks >> 2, ki = ks & 3;
                const uint32_t ain = base + 49152u + (uint32_t)ck*4096u +
                    SWZ128((uint32_t)((wm*16 + lrow)*128 + ki*32 + kseg*16));
                uint32_t ah[4];
                LDSM_X4(ah[0], ah[1], ah[2], ah[3], ain);
                uint32_t bh0[2] = {Bh4[ks][0], Bh4[ks][1]};
                uint32_t bh1[2] = {Bh4[ks][2], Bh4[ks][3]};
                uint32_t bh2v[2] = {Bh2[ks][0], Bh2[ks][1]};
                mma16816h(c[0], ah, bh0);
                mma16816h(c[1], ah, bh1);
                mma16816h(c[2], ah, bh2v);
            }
        }

        // write G to smem
        {
            const int l4 = lane >> 2, l2 = (lane & 3)*2;
            #pragma unroll
            for (int fn = 0; fn < 3; fn++) {
                const int col = wn*24 + fn*8 + l2;
                *(float2*)&Gs[(wm*16 + l4)*100 + col]     = make_float2(c[fn][0], c[fn][1]);
                *(float2*)&Gs[(wm*16 + l4 + 8)*100 + col] = make_float2(c[fn][2], c[fn][3]);
            }
        }
        __syncthreads();

        // ---- nonlinearity + h update ----
        {
            float4 gr = *(const float4*)&Gs[bb*100 + ju];
            float4 gz = *(const float4*)&Gs[bb*100 + 32 + ju];
            float4 gn = *(const float4*)&Gs[bb*100 + 64 + ju];
            float4 hp = *(const float4*)&Hprev[bb*36 + ju];
            float hn[4];
            const float* xr = &xr4.x;
            const float* xz = &xz4.x;
            const float* xn = &xn4.x;
            const float* grp = &gr.x;
            const float* gzp = &gz.x;
            const float* gnp = &gn.x;
            const float* hpp = &hp.x;
            #pragma unroll
            for (int i = 0; i < 4; i++) {
                float r = fsig(xr[i] + grp[i] + bhh_s[     ju + i]);
                float z = fsig(xz[i] + gzp[i] + bhh_s[32 + ju + i]);
                float n = ftanh(xn[i] + r*(gnp[i] + bhh_s[64 + ju + i]));
                hn[i] = (1.f - z)*n + z*hpp[i];
            }
            float4 hv = make_float4(hn[0], hn[1], hn[2], hn[3]);
            *(float4*)&Hprev[bb*36 + ju] = hv;
            __half2 h01 = __floats2half2_rn(hn[0], hn[1]);
            __half2 h23 = __floats2half2_rn(hn[2], hn[3]);
            uint32_t w0 = *(uint32_t*)&h01, w1 = *(uint32_t*)&h23;
            size_t oo = ((size_t)t_in*256 + bg)*512 + (size_t)dir*256 + j0 + ju;
            asm volatile("st.global.cg.v2.u32 [%0], {%1,%2};" :: "l"(obf + oo), "r"(w0), "r"(w1));
        }
        if (s_ != 511) {
            __syncthreads();
            if (tid == 0) {
                asm volatile("st.global.release.gpu.u32 [%0], %1;"
                    :: "l"(d_flags + (gid*8 + us)*32), "r"(LB + (unsigned)(s_ + 1)));
            }
        }
    }
}

// ---------------- single-pass fp16 warp-MMA GEMM ----------------
// C = A @ B^T, fp16 in, fp32 accum.
// MODE 0: xp1 = h1f @ wih1^T + bias.  grid (1024 mtiles, 6 ntiles, 2 dirs)
// MODE 1: fc1 partials per t.         grid (2 mtiles, 1, 512 t)
#define MMA_DSMEM (2*32768 + 1024)

template<int MODE>
__global__ void __launch_bounds__(256) mma_gemm_kernel(
    const __half* __restrict__ Af, const __half* __restrict__ Bf,
    const float* __restrict__ bias, float* __restrict__ outp) {
    extern __shared__ char dsm_raw[];
    const uint32_t raw  = smem_to_u32(dsm_raw);
    const uint32_t base = (raw + 1023u) & ~1023u;

    const int tid  = threadIdx.x;
    const int lane = tid & 31;
    const int wid  = tid >> 5;
    const int wm   = wid >> 2;
    const int wn   = wid & 3;

    size_t arow0, brow0, bstride, bk0;
    if (MODE == 0) {
        arow0 = (size_t)blockIdx.x * 128;
        brow0 = (size_t)blockIdx.z * 768 + (size_t)blockIdx.y * 128;
        bstride = 512; bk0 = 0;
    } else {
        arow0 = (size_t)blockIdx.z * 256 + (size_t)blockIdx.x * 128;
        brow0 = 0;
        bstride = 262144; bk0 = (size_t)blockIdx.z * 512;
    }

    float c[4][4][4];
    #pragma unroll
    for (int fm = 0; fm < 4; fm++)
    #pragma unroll
    for (int fn = 0; fn < 4; fn++)
    #pragma unroll
    for (int q = 0; q < 4; q++) c[fm][fn][q] = 0.f;

    auto issue = [&](int kc, int buf) {
        const uint32_t sbb = base + (uint32_t)buf*32768u;
        #pragma unroll
        for (int v = 0; v < 4; v++) {
            int vv = tid + v*256;
            int r = vv >> 3, seg = vv & 7;
            uint32_t sw = SWZ128((uint32_t)(r*128 + seg*16));
            size_t k  = (size_t)kc*64 + (size_t)seg*8;
            size_t ga = (arow0 + r)*512 + k;
            size_t gb = (brow0 + r)*bstride + bk0 + k;
            cp16(sbb +          sw, Af + ga);
            cp16(sbb + 16384u + sw, Bf + gb);
        }
    };

    issue(0, 0); CP_COMMIT();

    for (int kc = 0; kc < 8; kc++) {
        if (kc < 7) {
            issue(kc + 1, (kc + 1) & 1); CP_COMMIT();
            CP_WAIT(1);
        } else {
            CP_WAIT(0);
        }
        __syncthreads();

        const uint32_t sbb = base + (uint32_t)(kc & 1)*32768u;
        const int lrow = lane & 15, kseg = lane >> 4;
        const int g = lane >> 3, lr = lane & 7;
        const int nrow = ((g >> 1) & 1)*8 + lr;
        const int ks2 = g & 1;

        #pragma unroll
        for (int ki = 0; ki < 4; ki++) {
            uint32_t ahf[4][4];
            #pragma unroll
            for (int fm = 0; fm < 4; fm++) {
                uint32_t off = SWZ128((uint32_t)((wm*64 + fm*16 + lrow)*128 + ki*32 + kseg*16));
                LDSM_X4(ahf[fm][0], ahf[fm][1], ahf[fm][2], ahf[fm][3], sbb + off);
            }
            uint32_t bhf[4][2];
            #pragma unroll
            for (int fp = 0; fp < 2; fp++) {
                uint32_t off = SWZ128((uint32_t)((wn*32 + fp*16 + nrow)*128 + ki*32 + ks2*16));
                LDSM_X4(bhf[fp*2][0], bhf[fp*2][1], bhf[fp*2+1][0], bhf[fp*2+1][1], sbb + 16384u + off);
            }
            #pragma unroll
            for (int fm = 0; fm < 4; fm++)
            #pragma unroll
            for (int fn = 0; fn < 4; fn++)
                mma16816h(c[fm][fn], ahf[fm], bhf[fn]);
        }
        __syncthreads();
    }

    const int l4 = lane >> 2;
    const int l2 = (lane & 3)*2;
    #pragma unroll
    for (int fm = 0; fm < 4; fm++) {
        const int mr0 = wm*64 + fm*16 + l4;
        #pragma unroll
        for (int fn = 0; fn < 4; fn++) {
            const int col = wn*32 + fn*8 + l2;
            if (MODE == 0) {
                const int gcol = blockIdx.y*128 + col;
                float2 bv = *(const float2*)(bias + blockIdx.z*768 + gcol);
                size_t m0 = (size_t)blockIdx.z*131072 + (size_t)blockIdx.x*128 + mr0;
                *(float2*)(outp + m0*768 + gcol)       = make_float2(c[fm][fn][0] + bv.x, c[fm][fn][1] + bv.y);
                *(float2*)(outp + (m0 + 8)*768 + gcol) = make_float2(c[fm][fn][2] + bv.x, c[fm][fn][3] + bv.y);
            } else {
                size_t m0 = (size_t)blockIdx.z*256 + (size_t)blockIdx.x*128 + mr0;
                *(float2*)(outp + m0*128 + col)       = make_float2(c[fm][fn][0], c[fm][fn][1]);
                *(float2*)(outp + (m0 + 8)*128 + col) = make_float2(c[fm][fn][2], c[fm][fn][3]);
            }
        }
    }
}

// ---------------- final reduce + MLP head ----------------
__global__ void __launch_bounds__(128) fc_reduce_kernel(
    const float* __restrict__ b1, const float* __restrict__ W2,
    const float* __restrict__ b2, float* __restrict__ out) {
    const int b = blockIdx.x;
    const int o = threadIdx.x;
    const float* p = d_fc1p + (size_t)b*128 + o;
    float s0 = 0.f, s1 = 0.f, s2 = 0.f, s3 = 0.f;
    #pragma unroll 4
    for (int t = 0; t < 512; t += 4) {
        s0 += p[(size_t)(t+0)*32768];
        s1 += p[(size_t)(t+1)*32768];
        s2 += p[(size_t)(t+2)*32768];
        s3 += p[(size_t)(t+3)*32768];
    }
    float s = b1[o] + ((s0 + s1) + (s2 + s3));
    float v = s > 0.f ? s : 0.01f*s;
    float c = v * __ldg(W2 + o);
    __shared__ float red[128];
    red[o] = c;
    __syncthreads();
    for (int st = 64; st > 0; st >>= 1) {
        if (o < st) red[o] += red[o + st];
        __syncthreads();
    }
    if (o == 0) out[b] = 1.f/(1.f + expf(-(red[0] + b2[0])));
}

// ---------------- launch ----------------
extern "C" void kernel_launch(void* const* d_in, const int* in_sizes, int n_in,
                              void* d_out, int out_size) {
    const int*   inputs = (const int*)  d_in[0];
    const float* emb    = (const float*)d_in[1];
    const float* wih0   = (const float*)d_in[2];
    const float* whh0   = (const float*)d_in[3];
    const float* bih0   = (const float*)d_in[4];
    const float* bhh0   = (const float*)d_in[5];
    const float* wih1   = (const float*)d_in[6];
    const float* whh1   = (const float*)d_in[7];
    const float* bih1   = (const float*)d_in[8];
    const float* bhh1   = (const float*)d_in[9];
    const float* W1     = (const float*)d_in[10];
    const float* b1     = (const float*)d_in[11];
    const float* W2     = (const float*)d_in[12];
    const float* b2     = (const float*)d_in[13];
    float* out = (float*)d_out;

    cudaFuncSetAttribute((const void*)rec_mma_kernel<0>,
                         cudaFuncAttributeMaxDynamicSharedMemorySize, RECM_SMEM);
    cudaFuncSetAttribute((const void*)rec_mma_kernel<1>,
                         cudaFuncAttributeMaxDynamicSharedMemorySize, RECM_SMEM);
    cudaFuncSetAttribute((const void*)mma_gemm_kernel<0>,
                         cudaFuncAttributeMaxDynamicSharedMemorySize, MMA_DSMEM);
    cudaFuncSetAttribute((const void*)mma_gemm_kernel<1>,
                         cudaFuncAttributeMaxDynamicSharedMemorySize, MMA_DSMEM);

    __half *h1f, *h2f, *wihf, *W1f;
    cudaGetSymbolAddress((void**)&h1f, d_h1f);
    cudaGetSymbolAddress((void**)&h2f, d_h2f);
    cudaGetSymbolAddress((void**)&wihf, d_wihf);
    cudaGetSymbolAddress((void**)&W1f, d_W1f);
    float *xp1p, *fc1p;
    cudaGetSymbolAddress((void**)&xp1p, d_xp1);
    cudaGetSymbolAddress((void**)&fc1p, d_fc1p);

    proj0_kernel<<<130, 256>>>(emb, wih0, bih0);
    cvt_kernel<<<768, 256>>>(wih1, wihf, 196608);
    cvt_kernel<<<4096, 256>>>(W1, W1f, 8388608);
    reset_bar_kernel<<<16, 256>>>();
    rec_mma_kernel<0><<<128, 256, RECM_SMEM>>>(inputs, whh0, bhh0);
    mma_gemm_kernel<0><<<dim3(1024, 6, 2), 256, MMA_DSMEM>>>(h1f, wihf, bih1, xp1p);
    rec_mma_kernel<1><<<128, 256, RECM_SMEM>>>(inputs, whh1, bhh1);
    mma_gemm_kernel<1><<<dim3(2, 1, 512), 256, MMA_DSMEM>>>(h2f, W1f, nullptr, fc1p);
    fc_reduce_kernel<<<256, 128>>>(b1, W2, b2, out);
}